// round 8
// baseline (speedup 1.0000x reference)
#include <cuda_runtime.h>
#include <cuda_bf16.h>
#include <math.h>
#include <stdint.h>

#define N_TOKENS 65536
#define EMB_DIM  128
#define NUM_EMB  1024

// Output tuple flattened scalar-wise in reference-return order:
// (e_latent_loss, quantized_st[N,D], perplexity, encodings[N,K])
#define OUT_LOSS 0
#define OUT_Q    1
#define OUT_PERP (1 + N_TOKENS * EMB_DIM)        // 8388609
#define OUT_ENC  (2 + N_TOKENS * EMB_DIM)        // 8388610 (even -> 8B-aligned)

#define BM   128
#define NBLK (N_TOKENS / BM)     // 512
#define NTILES 8                 // 8 code tiles of 128
#define CAP  20                  // candidates per (token, tig) list

#define ROWB 272                 // 136 bf16/row: conflict-free fragment LDS

// smem byte offsets (dynamic, base 16B-aligned)
#define SM_A     0               // 34816: A tile bf16, 128 rows x 272B (persistent)
#define SM_B     34816           // 34816: B tile bf16, 128 rows x 272B
#define SM_CAND  69632           // 20480: uint16 cand[128*4][CAP]
#define SM_CNT   90112           // 1024:  uint16 cnt[128*4]
#define SM_SXD   91136           // 1024:  double sx[128]
#define SM_SBK   92160           // 512:   int bk[128]
#define SM_LRED  92672           // 2048:  double lred[256]
#define SM_LACC  94720           // 2048:  double lacc[256]
#define DSMEM    96768

__device__ __align__(16) __nv_bfloat16 g_ebf[NUM_EMB * EMB_DIM]; // bf16 codebook
__device__ float  g_be[NUM_EMB];     // fl32 of exact ||e_k||^2
__device__ int    g_hist[NUM_EMB];   // code counts
__device__ double g_lpart[NBLK];     // per-block loss partials
__device__ unsigned int g_done;      // last-block-done counter

// baseline-PTX tensor op (compute_103-safe): m16n8k16 bf16 -> f32
__device__ __forceinline__ void mma16816(float* d,
                                         uint32_t a0, uint32_t a1,
                                         uint32_t a2, uint32_t a3,
                                         uint32_t b0, uint32_t b1) {
    asm volatile(
        "mma.sync.aligned.m16n8k16.row.col.f32.bf16.bf16.f32 "
        "{%0,%1,%2,%3}, {%4,%5,%6,%7}, {%8,%9}, {%0,%1,%2,%3};"
        : "+f"(d[0]), "+f"(d[1]), "+f"(d[2]), "+f"(d[3])
        : "r"(a0), "r"(a1), "r"(a2), "r"(a3), "r"(b0), "r"(b1));
}

// exact sequential-k fp32 dot (reference accumulation order), float4 loads
__device__ __forceinline__ float exact_dot(const float* __restrict__ xr,
                                           const float* __restrict__ er) {
    const float4* x4 = (const float4*)xr;
    const float4* e4 = (const float4*)er;
    float dot = 0.f;
#pragma unroll 4
    for (int q = 0; q < EMB_DIM / 4; q++) {
        float4 xv = x4[q], ev = e4[q];
        dot = __fmaf_rn(xv.x, ev.x, dot);
        dot = __fmaf_rn(xv.y, ev.y, dot);
        dot = __fmaf_rn(xv.z, ev.z, dot);
        dot = __fmaf_rn(xv.w, ev.w, dot);
    }
    return dot;
}

// ---------------------------------------------------------------------------
// prep: bf16 codebook + exact fp32 norms + zero hist/done. Warp per code.
// ---------------------------------------------------------------------------
__global__ void vq_prep_kernel(const float* __restrict__ emb) {
    const int gtid = blockIdx.x * 256 + threadIdx.x;   // 32768 threads
    const int code = gtid >> 5, lane = gtid & 31;
    float4 v = ((const float4*)(emb + (size_t)code * EMB_DIM))[lane];
    double s;
    { double a = v.x, b = v.y, c = v.z, d = v.w; s = a*a + b*b + c*c + d*d; }
    __nv_bfloat162 p0 = __float22bfloat162_rn(make_float2(v.x, v.y));
    __nv_bfloat162 p1 = __float22bfloat162_rn(make_float2(v.z, v.w));
    uint2 u; u.x = *(unsigned*)&p0; u.y = *(unsigned*)&p1;
    *(uint2*)&g_ebf[(size_t)code * EMB_DIM + lane * 4] = u;
#pragma unroll
    for (int off = 16; off > 0; off >>= 1)
        s += __shfl_down_sync(0xffffffffu, s, off);
    if (lane == 0) { g_be[code] = (float)s; g_hist[code] = 0; }
    if (gtid == 0) g_done = 0;
}

// ---------------------------------------------------------------------------
// main: single-pass HMMA screening (running-min margin collection, CAP=20)
// with A and B fragments streamed from smem (low register pressure), then
// exact fp32 rescore (R3 bit-identical chain) + fused outputs.
// ---------------------------------------------------------------------------
__global__ __launch_bounds__(256, 2)
void vq_main_kernel(const float* __restrict__ x,
                    const float* __restrict__ emb,
                    float* __restrict__ out)
{
    extern __shared__ __align__(16) char dsm[];
    char*      sA   = dsm + SM_A;
    char*      sB   = dsm + SM_B;
    uint16_t*  cand = (uint16_t*)(dsm + SM_CAND);
    uint16_t*  cnts = (uint16_t*)(dsm + SM_CNT);
    double*    sxd  = (double*)(dsm + SM_SXD);
    int*       s_bk = (int*)(dsm + SM_SBK);
    double*    lred = (double*)(dsm + SM_LRED);
    double*    lacc = (double*)(dsm + SM_LACC);

    const int tid  = threadIdx.x;    // 256
    const int wid  = tid >> 5;       // 8 warps; warp owns tokens 16w..16w+15
    const int lane = tid & 31;
    const int gID  = lane >> 2;      // 0..7
    const int tig  = lane & 3;       // 0..3
    const int m0   = blockIdx.x * BM;

    // ---- zero this block's one-hot rows (big DRAM op, overlaps all) ----
    {
        float2* enc2 = (float2*)(out + OUT_ENC);
        size_t base = (size_t)m0 * (NUM_EMB / 2);
        for (int i = tid; i < BM * NUM_EMB / 2; i += 256)
            enc2[base + i] = make_float2(0.f, 0.f);
    }

    // ---- A tile: x rows -> bf16 smem (row-major, 272B stride); sx double ----
    if (tid < 128) {
        const float4* xr = (const float4*)(x + (size_t)(m0 + tid) * EMB_DIM);
        char* row = sA + tid * ROWB;
        double sx = 0.0;
#pragma unroll 8
        for (int c = 0; c < 32; c++) {
            float4 v = xr[c];
            __nv_bfloat162 p0 = __float22bfloat162_rn(make_float2(v.x, v.y));
            __nv_bfloat162 p1 = __float22bfloat162_rn(make_float2(v.z, v.w));
            uint2 u; u.x = *(unsigned*)&p0; u.y = *(unsigned*)&p1;
            *(uint2*)(row + c * 8) = u;
            double a = v.x, b = v.y, cc = v.z, d = v.w;
            sx += a * a; sx += b * b; sx += cc * cc; sx += d * d;
        }
        sxd[tid] = sx;
    }
    __syncthreads();

    const int tok0 = wid * 16 + gID;        // local token of acc rows 0..7
    const int tok1 = tok0 + 8;
    const float d0 = 2.5e-4f * sqrtf((float)sxd[tok0]) + 2e-4f;
    const float d1 = 2.5e-4f * sqrtf((float)sxd[tok1]) + 2e-4f;
    float rm0 = INFINITY, rm1 = INFINITY;
    int   cnt0 = 0, cnt1 = 0;
    uint16_t* L0 = cand + (tok0 * 4 + tig) * CAP;
    uint16_t* L1 = cand + (tok1 * 4 + tig) * CAP;

    // per-warp A fragment base pointers (smem-resident all kernel)
    const char* pa0 = sA + (size_t)tok0 * ROWB + 4 * tig;
    const char* pa1 = pa0 + 8 * ROWB;

    // ---- single-pass screening over 8 code tiles of 128 ----
    for (int t = 0; t < NTILES; t++) {
        // load B tile: 2 threads per code row, uint4 (8 bf16) x 8
        {
            const int r2 = tid >> 1, kh = tid & 1;
            const uint4* src = (const uint4*)(g_ebf +
                ((size_t)(t * 128 + r2) * EMB_DIM + kh * 64));
            char* dst = sB + r2 * ROWB + kh * 128;
#pragma unroll
            for (int j = 0; j < 8; j++)
                *(uint4*)(dst + j * 16) = src[j];
        }
        __syncthreads();

        // 16 n-tiles of 8 codes
        for (int nt = 0; nt < 16; nt++) {
            const char* pb = sB + (nt * 8 + gID) * ROWB + 4 * tig;
            float ac[4] = {0.f, 0.f, 0.f, 0.f};
#pragma unroll
            for (int s = 0; s < 8; s++) {
                uint32_t a0 = *(const uint32_t*)(pa0 + 32 * s);
                uint32_t a1 = *(const uint32_t*)(pa1 + 32 * s);
                uint32_t a2 = *(const uint32_t*)(pa0 + 32 * s + 16);
                uint32_t a3 = *(const uint32_t*)(pa1 + 32 * s + 16);
                uint32_t b0 = *(const uint32_t*)(pb + 32 * s);
                uint32_t b1 = *(const uint32_t*)(pb + 32 * s + 16);
                mma16816(ac, a0, a1, a2, a3, b0, b1);
            }
            // scores + running-min margin collection
            const int c0 = t * 128 + nt * 8 + 2 * tig;
            float2 be2 = __ldg((const float2*)(g_be + c0));
            float s00 = __fmaf_rn(-2.f, ac[0], be2.x);
            float s01 = __fmaf_rn(-2.f, ac[1], be2.y);
            float s10 = __fmaf_rn(-2.f, ac[2], be2.x);
            float s11 = __fmaf_rn(-2.f, ac[3], be2.y);
            if (s00 - rm0 <= d0) { if (cnt0 < CAP) L0[cnt0] = (uint16_t)c0;     cnt0++; }
            rm0 = fminf(rm0, s00);
            if (s01 - rm0 <= d0) { if (cnt0 < CAP) L0[cnt0] = (uint16_t)(c0+1); cnt0++; }
            rm0 = fminf(rm0, s01);
            if (s10 - rm1 <= d1) { if (cnt1 < CAP) L1[cnt1] = (uint16_t)c0;     cnt1++; }
            rm1 = fminf(rm1, s10);
            if (s11 - rm1 <= d1) { if (cnt1 < CAP) L1[cnt1] = (uint16_t)(c0+1); cnt1++; }
            rm1 = fminf(rm1, s11);
        }
        __syncthreads();   // all B reads done before next tile overwrite
    }
    cnts[tok0 * 4 + tig] = (uint16_t)cnt0;
    cnts[tok1 * 4 + tig] = (uint16_t)cnt1;
    __syncthreads();

    // ---- phase 2: exact rescore (R3 bit-exact arithmetic, float4 loads) ----
    if (tid < 128) {
        const int row = m0 + tid;
        const float sxe = (float)sxd[tid];
        const float* xr = x + (size_t)row * EMB_DIM;
        float bv = INFINITY;
        int   bk = 1 << 30;
        bool ovf = false;
#pragma unroll
        for (int li = 0; li < 4; li++)
            if (cnts[tid * 4 + li] > CAP) ovf = true;
        if (ovf) {
            // certified-margin overflow fallback (P ~ 1e-8): full exact scan
            for (int k = 0; k < NUM_EMB; k++) {
                float dot = exact_dot(xr, emb + (size_t)k * EMB_DIM);
                float d = __fsub_rn(__fadd_rn(sxe, g_be[k]),
                                    __fmul_rn(2.0f, dot));
                if (d < bv || (d == bv && k < bk)) { bv = d; bk = k; }
            }
        } else {
#pragma unroll
            for (int li = 0; li < 4; li++) {
                const uint16_t* ls = cand + (tid * 4 + li) * CAP;
                const int nc = cnts[tid * 4 + li];
                for (int i = 0; i < nc; i++) {
                    const int k = ls[i];
                    float dot = exact_dot(xr, emb + (size_t)k * EMB_DIM);
                    float d = __fsub_rn(__fadd_rn(sxe, g_be[k]),
                                        __fmul_rn(2.0f, dot));
                    if (d < bv || (d == bv && k < bk)) { bv = d; bk = k; }
                }
            }
        }
        s_bk[tid] = bk;
        out[(size_t)OUT_ENC + (size_t)row * NUM_EMB + bk] = 1.0f;
        atomicAdd(&g_hist[bk], 1);   // integer atomic: deterministic
    }
    __syncthreads();

    // ---- cooperative coalesced quantized_st + loss (32-bit stores) ----
    double lsum = 0.0;
    float* oq = out + OUT_Q + (size_t)m0 * EMB_DIM;
    const float* xq = x + (size_t)m0 * EMB_DIM;
    for (int e = tid; e < BM * EMB_DIM; e += 256) {
        const int row = e >> 7;
        const int col = e & 127;
        const float xv = xq[e];
        const float qv = emb[(size_t)s_bk[row] * EMB_DIM + col];
        const float d  = __fsub_rn(qv, xv);
        oq[e] = __fadd_rn(xv, d);        // fl(x + fl(q-x)), exact STE math
        lsum += (double)d * (double)d;
    }
    lred[tid] = lsum;
    __syncthreads();
    for (int s = 128; s > 0; s >>= 1) {
        if (tid < s) lred[tid] += lred[tid + s];
        __syncthreads();
    }
    if (tid == 0) g_lpart[blockIdx.x] = lred[0];

    // ---- last block computes the scalars (fused finalize) ----
    __shared__ bool is_last;
    __threadfence();
    if (tid == 0) {
        unsigned v = atomicAdd(&g_done, 1u);
        is_last = (v == NBLK - 1);
    }
    __syncthreads();
    if (!is_last) return;

    double ent = 0.0;
#pragma unroll
    for (int b = 0; b < 4; b++) {
        double pr = (double)g_hist[tid * 4 + b] / (double)N_TOKENS;
        ent += pr * log(pr + 1e-10);
    }
    double ls = 0.0;
#pragma unroll
    for (int b = 0; b < 2; b++) ls += g_lpart[tid * 2 + b];
    lred[tid] = ent;
    lacc[tid] = ls;
    __syncthreads();
    for (int s = 128; s > 0; s >>= 1) {
        if (tid < s) { lred[tid] += lred[tid + s]; lacc[tid] += lacc[tid + s]; }
        __syncthreads();
    }
    if (tid == 0) {
        out[OUT_PERP] = (float)exp(-lred[0]);
        out[OUT_LOSS] = (float)(lacc[0] / ((double)N_TOKENS * (double)EMB_DIM));
    }
}

// ---------------------------------------------------------------------------
extern "C" void kernel_launch(void* const* d_in, const int* in_sizes, int n_in,
                              void* d_out, int out_size) {
    const float* x   = (const float*)d_in[0];   // inputs [65536,128]
    const float* emb = (const float*)d_in[1];   // emb_w  [1024,128]
    float* out = (float*)d_out;

    cudaFuncSetAttribute(vq_main_kernel,
                         cudaFuncAttributeMaxDynamicSharedMemorySize, DSMEM);
    vq_prep_kernel<<<NUM_EMB * 32 / 256, 256>>>(emb);
    vq_main_kernel<<<NBLK, 256, DSMEM>>>(x, emb, out);
}

// round 9
// speedup vs baseline: 1.8577x; 1.8577x over previous
#include <cuda_runtime.h>
#include <math.h>
#include <stdint.h>

#define N_TOKENS 65536
#define EMB_DIM  128
#define NUM_EMB  1024

// Output tuple flattened scalar-wise in reference-return order:
// (e_latent_loss, quantized_st[N,D], perplexity, encodings[N,K])
#define OUT_LOSS 0
#define OUT_Q    1
#define OUT_PERP (1 + N_TOKENS * EMB_DIM)        // 8388609
#define OUT_ENC  (2 + N_TOKENS * EMB_DIM)        // 8388610 (even -> 8B-aligned)

#define BM   128
#define NBLK (N_TOKENS / BM)     // 512
#define SAS  132                 // smem tile row stride (int32 words)
#define CAP  16                  // candidates per token

// smem byte offsets (dynamic)
#define SM_A     0        // 16896: A int8 tile as int32 [32 kgroups][132]
#define SM_B     16896    // 16896: B int8 tile
#define SM_RED   33792    // 8192:  float redv[128][16]
#define SM_THR   41984    // 512:   float thr[128]
#define SM_RXS   42496    // 512:   float rxs[128]
#define SM_CNT   43008    // 512:   int   scnt[128]
#define SM_LIST  43520    // 4096:  uint16 slist[128][CAP]
#define SM_SBK   47616    // 512:   int bk[128]
#define SM_LRED  48128    // 2048:  double lred[256]
#define SM_LACC  50176    // 2048:  double lacc[256]
#define DSMEM    52224

__device__ int    g_eq[NUM_EMB * 32];    // int8-packed codebook (k-groups of 4)
__device__ int    g_xq[N_TOKENS * 32];   // int8-packed tokens
__device__ float  g_be[NUM_EMB];         // fl32 of exact ||e_k||^2
__device__ float  g_c2e[NUM_EMB];        // 2*emax_k/127  (dequant*2 factor)
__device__ float  g_sx[N_TOKENS];        // fl32 of exact ||x_n||^2
__device__ float  g_rxs[N_TOKENS];       // amax_n/127 (x dequant factor)
__device__ float  g_s1x[N_TOKENS];       // sum |x_n|
__device__ unsigned g_qe_bits;           // global max qe = emax/254 (float bits)
__device__ unsigned g_s1e_bits;          // global max sum|e_k| (float bits)
__device__ int    g_hist[NUM_EMB];
__device__ double g_lpart[NBLK];
__device__ unsigned int g_done;

// ---------------- warp reduce helpers (fixed order -> deterministic) --------
__device__ __forceinline__ float wmaxf(float v) {
#pragma unroll
    for (int o = 16; o > 0; o >>= 1) v = fmaxf(v, __shfl_down_sync(~0u, v, o));
    return __shfl_sync(~0u, v, 0);
}
__device__ __forceinline__ float wsumf(float v) {
#pragma unroll
    for (int o = 16; o > 0; o >>= 1) v += __shfl_down_sync(~0u, v, o);
    return __shfl_sync(~0u, v, 0);
}
__device__ __forceinline__ double wsumd(double v) {
#pragma unroll
    for (int o = 16; o > 0; o >>= 1) v += __shfl_down_sync(~0u, v, o);
    return v;   // valid on lane 0
}
__device__ __forceinline__ int q8(float v) {
    int q = __float2int_rn(v);
    return q > 127 ? 127 : (q < -127 ? -127 : q);
}

// exact sequential-k fp32 dot (reference accumulation order), float4 loads
__device__ __forceinline__ float exact_dot(const float* __restrict__ xr,
                                           const float* __restrict__ er) {
    const float4* x4 = (const float4*)xr;
    const float4* e4 = (const float4*)er;
    float dot = 0.f;
#pragma unroll 4
    for (int q = 0; q < EMB_DIM / 4; q++) {
        float4 xv = x4[q], ev = e4[q];
        dot = __fmaf_rn(xv.x, ev.x, dot);
        dot = __fmaf_rn(xv.y, ev.y, dot);
        dot = __fmaf_rn(xv.z, ev.z, dot);
        dot = __fmaf_rn(xv.w, ev.w, dot);
    }
    return dot;
}

// ---------------------------------------------------------------------------
__global__ void vq_init_kernel() {
    g_qe_bits = 0u; g_s1e_bits = 0u; g_done = 0u;
}

// prep: per code (warp): norms, abs-max, int8 quantize, global maxima
__global__ void vq_prep_kernel(const float* __restrict__ emb) {
    const int wid = threadIdx.x >> 5, lane = threadIdx.x & 31;
    const int code = blockIdx.x * 8 + wid;
    float4 v = ((const float4*)emb)[code * 32 + lane];
    float am = fmaxf(fmaxf(fabsf(v.x), fabsf(v.y)), fmaxf(fabsf(v.z), fabsf(v.w)));
    float s1 = fabsf(v.x) + fabsf(v.y) + fabsf(v.z) + fabsf(v.w);
    double sd; { double a=v.x,b=v.y,c=v.z,d=v.w; sd = a*a + b*b + c*c + d*d; }
    float emax = fmaxf(wmaxf(am), 1e-30f);
    float s1e  = wsumf(s1);
    double se  = wsumd(sd);
    float ses = 127.0f / emax;
    int pack = (q8(v.x * ses) & 0xff) | ((q8(v.y * ses) & 0xff) << 8)
             | ((q8(v.z * ses) & 0xff) << 16) | ((q8(v.w * ses) & 0xff) << 24);
    g_eq[code * 32 + lane] = pack;
    if (lane == 0) {
        g_be[code]  = (float)se;
        g_c2e[code] = 2.0f * emax / 127.0f;
        g_hist[code] = 0;
        atomicMax(&g_qe_bits, __float_as_uint(emax / 254.0f));
        atomicMax(&g_s1e_bits, __float_as_uint(s1e));
    }
}

// per-token: norms, abs-max, int8 quantize
__global__ void vq_sx_kernel(const float* __restrict__ x) {
    const int wid = threadIdx.x >> 5, lane = threadIdx.x & 31;
    const int row = blockIdx.x * 8 + wid;
    float4 v = ((const float4*)x)[row * 32 + lane];
    float am = fmaxf(fmaxf(fabsf(v.x), fabsf(v.y)), fmaxf(fabsf(v.z), fabsf(v.w)));
    float s1 = fabsf(v.x) + fabsf(v.y) + fabsf(v.z) + fabsf(v.w);
    double sd; { double a=v.x,b=v.y,c=v.z,d=v.w; sd = a*a + b*b + c*c + d*d; }
    float amax = fmaxf(wmaxf(am), 1e-30f);
    float s1x  = wsumf(s1);
    double sx  = wsumd(sd);
    float sxs = 127.0f / amax;
    int pack = (q8(v.x * sxs) & 0xff) | ((q8(v.y * sxs) & 0xff) << 8)
             | ((q8(v.z * sxs) & 0xff) << 16) | ((q8(v.w * sxs) & 0xff) << 24);
    g_xq[row * 32 + lane] = pack;
    if (lane == 0) {
        g_sx[row]  = (float)sx;
        g_rxs[row] = amax / 127.0f;
        g_s1x[row] = s1x;
    }
}

// transpose-load a 128-row x 32-word int8 tile into k-major smem [32][SAS]
__device__ __forceinline__ void load_tile(int* dst, const int* __restrict__ gsrc,
                                          int row0, int tid) {
    const int lr = tid >> 3, lc = tid & 7;
#pragma unroll
    for (int p = 0; p < 4; p++) {
        int r = p * 32 + lr;
        int4 w = ((const int4*)gsrc)[(size_t)(row0 + r) * 8 + lc];
        dst[(lc * 4 + 0) * SAS + r] = w.x;
        dst[(lc * 4 + 1) * SAS + r] = w.y;
        dst[(lc * 4 + 2) * SAS + r] = w.z;
        dst[(lc * 4 + 3) * SAS + r] = w.w;
    }
}

// ---------------------------------------------------------------------------
// main: two-pass int8 DP4A screening GEMM (pass A: per-token approx min;
// pass B: collect codes within certified margin), exact fp32 rescore (R3
// bit-identical chain) + fused outputs.
// ---------------------------------------------------------------------------
__global__ __launch_bounds__(256, 2)
void vq_main_kernel(const float* __restrict__ x,
                    const float* __restrict__ emb,
                    float* __restrict__ out)
{
    extern __shared__ __align__(16) char dsm[];
    int*       sAq  = (int*)(dsm + SM_A);
    int*       sBq  = (int*)(dsm + SM_B);
    float*     redv = (float*)(dsm + SM_RED);
    float*     sthr = (float*)(dsm + SM_THR);
    float*     srxs = (float*)(dsm + SM_RXS);
    int*       scnt = (int*)(dsm + SM_CNT);
    uint16_t*  slist= (uint16_t*)(dsm + SM_LIST);
    int*       s_bk = (int*)(dsm + SM_SBK);
    double*    lred = (double*)(dsm + SM_LRED);
    double*    lacc = (double*)(dsm + SM_LACC);

    const int tid = threadIdx.x;     // 256
    const int tx  = tid & 15;        // codes tx*8..tx*8+7 within tile
    const int ty  = tid >> 4;        // tokens ty*8..ty*8+7
    const int m0  = blockIdx.x * BM;

    // ---- zero this block's one-hot rows (big DRAM op, overlaps all) ----
    {
        float2* enc2 = (float2*)(out + OUT_ENC);
        size_t base = (size_t)m0 * (NUM_EMB / 2);
        for (int i = tid; i < BM * NUM_EMB / 2; i += 256)
            enc2[base + i] = make_float2(0.f, 0.f);
    }

    // ---- A tile (resident all kernel) + per-token dequant factors ----
    load_tile(sAq, g_xq, m0, tid);
    if (tid < 128) srxs[tid] = g_rxs[m0 + tid];

    float rmin[8];
#pragma unroll
    for (int i = 0; i < 8; i++) rmin[i] = INFINITY;
    __syncthreads();

    const int* pa = sAq + ty * 8;
    const int* pb = sBq + tx * 8;

    // ================= PASS A: approx min only =================
    for (int ct = 0; ct < 8; ct++) {
        load_tile(sBq, g_eq, ct * 128, tid);
        __syncthreads();
        int acc[8][8];
#pragma unroll
        for (int i = 0; i < 8; i++)
#pragma unroll
            for (int j = 0; j < 8; j++) acc[i][j] = 0;
#pragma unroll 4
        for (int g = 0; g < 32; g++) {
            int4 a03 = *(const int4*)(pa + g * SAS);
            int4 a47 = *(const int4*)(pa + g * SAS + 4);
            int4 b03 = *(const int4*)(pb + g * SAS);
            int4 b47 = *(const int4*)(pb + g * SAS + 4);
            int aw[8] = {a03.x,a03.y,a03.z,a03.w,a47.x,a47.y,a47.z,a47.w};
            int bw[8] = {b03.x,b03.y,b03.z,b03.w,b47.x,b47.y,b47.z,b47.w};
#pragma unroll
            for (int i = 0; i < 8; i++)
#pragma unroll
                for (int j = 0; j < 8; j++)
                    acc[i][j] = __dp4a(aw[i], bw[j], acc[i][j]);
        }
#pragma unroll
        for (int j = 0; j < 8; j++) {
            const int k = ct * 128 + tx * 8 + j;
            const float be = __ldg(&g_be[k]);
            const float ce = __ldg(&g_c2e[k]);
#pragma unroll
            for (int i = 0; i < 8; i++) {
                float s = __fmaf_rn(-(float)acc[i][j],
                                    __fmul_rn(ce, srxs[ty * 8 + i]), be);
                rmin[i] = fminf(rmin[i], s);
            }
        }
        __syncthreads();
    }

    // ---- reduce to per-token approx min, build certified thresholds ----
#pragma unroll
    for (int i = 0; i < 8; i++) redv[(ty * 8 + i) * 16 + tx] = rmin[i];
    __syncthreads();
    if (tid < 128) {
        float tm = redv[tid * 16];
#pragma unroll
        for (int t = 1; t < 16; t++) tm = fminf(tm, redv[tid * 16 + t]);
        const float rx  = srxs[tid];
        const float qx  = 0.5f * rx;
        const float qe  = __uint_as_float(g_qe_bits);
        const float s1e = __uint_as_float(g_s1e_bits);
        const float s1x = g_s1x[m0 + tid];
        const float delta = 4.0f * (s1x * qe + qx * s1e + 128.0f * qx * qe) + 6e-5f;
        sthr[tid] = tm + delta;
        scnt[tid] = 0;
    }
    __syncthreads();

    // ================= PASS B: collect candidates =================
    for (int ct = 0; ct < 8; ct++) {
        load_tile(sBq, g_eq, ct * 128, tid);
        __syncthreads();
        int acc[8][8];
#pragma unroll
        for (int i = 0; i < 8; i++)
#pragma unroll
            for (int j = 0; j < 8; j++) acc[i][j] = 0;
#pragma unroll 4
        for (int g = 0; g < 32; g++) {
            int4 a03 = *(const int4*)(pa + g * SAS);
            int4 a47 = *(const int4*)(pa + g * SAS + 4);
            int4 b03 = *(const int4*)(pb + g * SAS);
            int4 b47 = *(const int4*)(pb + g * SAS + 4);
            int aw[8] = {a03.x,a03.y,a03.z,a03.w,a47.x,a47.y,a47.z,a47.w};
            int bw[8] = {b03.x,b03.y,b03.z,b03.w,b47.x,b47.y,b47.z,b47.w};
#pragma unroll
            for (int i = 0; i < 8; i++)
#pragma unroll
                for (int j = 0; j < 8; j++)
                    acc[i][j] = __dp4a(aw[i], bw[j], acc[i][j]);
        }
#pragma unroll
        for (int j = 0; j < 8; j++) {
            const int k = ct * 128 + tx * 8 + j;
            const float be = __ldg(&g_be[k]);
            const float ce = __ldg(&g_c2e[k]);
#pragma unroll
            for (int i = 0; i < 8; i++) {
                float s = __fmaf_rn(-(float)acc[i][j],
                                    __fmul_rn(ce, srxs[ty * 8 + i]), be);
                if (s <= sthr[ty * 8 + i]) {
                    int idx = atomicAdd(&scnt[ty * 8 + i], 1);
                    if (idx < CAP) slist[(ty * 8 + i) * CAP + idx] = (uint16_t)k;
                }
            }
        }
        __syncthreads();
    }

    // ---- phase 2: exact rescore (R3 bit-exact arithmetic) ----
    if (tid < 128) {
        const int row = m0 + tid;
        const float sxe = g_sx[row];
        const float* xr = x + (size_t)row * EMB_DIM;
        float bv = INFINITY;
        int   bk = 1 << 30;
        const int nc = scnt[tid];
        if (nc > CAP) {
            // certified-margin overflow fallback (P ~ 1e-7): full exact scan
            for (int k = 0; k < NUM_EMB; k++) {
                float dot = exact_dot(xr, emb + (size_t)k * EMB_DIM);
                float d = __fsub_rn(__fadd_rn(sxe, g_be[k]),
                                    __fmul_rn(2.0f, dot));
                if (d < bv || (d == bv && k < bk)) { bv = d; bk = k; }
            }
        } else {
            for (int i = 0; i < nc; i++) {
                const int k = slist[tid * CAP + i];
                float dot = exact_dot(xr, emb + (size_t)k * EMB_DIM);
                float d = __fsub_rn(__fadd_rn(sxe, g_be[k]),
                                    __fmul_rn(2.0f, dot));
                if (d < bv || (d == bv && k < bk)) { bv = d; bk = k; }
            }
        }
        s_bk[tid] = bk;
        out[(size_t)OUT_ENC + (size_t)row * NUM_EMB + bk] = 1.0f;
        atomicAdd(&g_hist[bk], 1);   // integer atomic: deterministic
    }
    __syncthreads();

    // ---- cooperative coalesced quantized_st + loss (32-bit stores) ----
    double lsum = 0.0;
    float* oq = out + OUT_Q + (size_t)m0 * EMB_DIM;
    const float* xq = x + (size_t)m0 * EMB_DIM;
    for (int e = tid; e < BM * EMB_DIM; e += 256) {
        const int row = e >> 7;
        const int col = e & 127;
        const float xv = xq[e];
        const float qv = emb[(size_t)s_bk[row] * EMB_DIM + col];
        const float d  = __fsub_rn(qv, xv);
        oq[e] = __fadd_rn(xv, d);        // fl(x + fl(q-x)), exact STE math
        lsum += (double)d * (double)d;
    }
    lred[tid] = lsum;
    __syncthreads();
    for (int s = 128; s > 0; s >>= 1) {
        if (tid < s) lred[tid] += lred[tid + s];
        __syncthreads();
    }
    if (tid == 0) g_lpart[blockIdx.x] = lred[0];

    // ---- last block computes the scalars (fused finalize) ----
    __shared__ bool is_last;
    __threadfence();
    if (tid == 0) {
        unsigned v = atomicAdd(&g_done, 1u);
        is_last = (v == NBLK - 1);
    }
    __syncthreads();
    if (!is_last) return;

    double ent = 0.0;
#pragma unroll
    for (int b = 0; b < 4; b++) {
        double pr = (double)g_hist[tid * 4 + b] / (double)N_TOKENS;
        ent += pr * log(pr + 1e-10);
    }
    double ls = 0.0;
#pragma unroll
    for (int b = 0; b < 2; b++) ls += g_lpart[tid * 2 + b];
    lred[tid] = ent;
    lacc[tid] = ls;
    __syncthreads();
    for (int s = 128; s > 0; s >>= 1) {
        if (tid < s) { lred[tid] += lred[tid + s]; lacc[tid] += lacc[tid + s]; }
        __syncthreads();
    }
    if (tid == 0) {
        out[OUT_PERP] = (float)exp(-lred[0]);
        out[OUT_LOSS] = (float)(lacc[0] / ((double)N_TOKENS * (double)EMB_DIM));
    }
}

// ---------------------------------------------------------------------------
extern "C" void kernel_launch(void* const* d_in, const int* in_sizes, int n_in,
                              void* d_out, int out_size) {
    const float* x   = (const float*)d_in[0];   // inputs [65536,128]
    const float* emb = (const float*)d_in[1];   // emb_w  [1024,128]
    float* out = (float*)d_out;

    cudaFuncSetAttribute(vq_main_kernel,
                         cudaFuncAttributeMaxDynamicSharedMemorySize, DSMEM);
    vq_init_kernel<<<1, 1>>>();
    vq_prep_kernel<<<NUM_EMB / 8, 256>>>(emb);
    vq_sx_kernel<<<N_TOKENS / 8, 256>>>(x);
    vq_main_kernel<<<NBLK, 256, DSMEM>>>(x, emb, out);
}